// round 12
// baseline (speedup 1.0000x reference)
#include <cuda_runtime.h>
#include <cuda_fp16.h>
#include <cstdint>

#define B_SZ 16384
#define F_SZ 9000
#define BK   32
#define NCH  282             // ceil(9000/32); last chunk 8 valid k
#define PL   4096            // W sub-plane bytes: 128 rows x 32B
#define PLA  8192            // A sub-plane bytes: 256 rows x 32B
// stage layout: A_s0[8K] | A_s1[8K] | W_s0[4K] | W_s1[4K]
#define W_OFF   16384
#define WCHUNK  8192         // W bytes per chunk in g_wh (2 planes)
#define STG_SZ  24576
#define SMEM_DYN (2 * STG_SZ)   // 49152 B exactly; no static smem in ft kernel

__device__ float g_scratch[B_SZ * 256];
__device__ int g_mode;
__device__ float g_wsum[128];
__device__ unsigned char g_wh[NCH * WCHUNK];   // per-chunk [W_s0|W_s1] fp16, SWZ layout

__device__ __forceinline__ float screlu(float x) {
    x = fminf(fmaxf(x, 0.0f), 1.0f);
    return x * x;
}

__device__ __forceinline__ uint32_t smem_u32(const void* p) {
    uint32_t a;
    asm("{ .reg .u64 t; cvta.to.shared.u64 t, %1; cvt.u32.u64 %0, t; }" : "=r"(a) : "l"(p));
    return a;
}

// XOR swizzle for 32B rows: row r, 16B-half h -> conflict-free ldmatrix/STS
#define SWZ(r, h) ((uint32_t)((r) * 32 + (((h) ^ (((r) >> 2) & 1)) << 4)))

__device__ __forceinline__ uint32_t h2u(__half2 h) {
    uint32_t u;
    *(__half2*)&u = h;
    return u;
}
__device__ __forceinline__ uint32_t cvtH2(float x0, float x1) {
    return h2u(__floats2half2_rn(x0, x1));
}

#define LDSM_X4(r, addr)                                                         \
    asm volatile("ldmatrix.sync.aligned.m8n8.x4.shared.b16 {%0,%1,%2,%3}, [%4];" \
                 : "=r"((r)[0]), "=r"((r)[1]), "=r"((r)[2]), "=r"((r)[3])        \
                 : "r"(addr))

#define MMA16816(c, a, bb0, bb1)                                                 \
    asm volatile("mma.sync.aligned.m16n8k16.row.col.f32.f16.f16.f32 "            \
                 "{%0,%1,%2,%3}, {%4,%5,%6,%7}, {%8,%9}, {%0,%1,%2,%3};"         \
                 : "+f"((c)[0]), "+f"((c)[1]), "+f"((c)[2]), "+f"((c)[3])        \
                 : "r"((a)[0]), "r"((a)[1]), "r"((a)[2]), "r"((a)[3]),           \
                   "r"(bb0), "r"(bb1))

// ---------------------------------------------------------------------------
// Kernel 0: W prep (fp16 1-limb, SWZ layout) + stm dtype sniff (extra block).
// ---------------------------------------------------------------------------
__global__ void wprep_kernel(const float* __restrict__ ftw,
                             const unsigned char* __restrict__ stm) {
    const int t = threadIdx.x;
    if (blockIdx.x == NCH) {
        __shared__ int fFloat, fBool;
        if (t == 0) { fFloat = 0; fBool = 0; }
        __syncthreads();
        int lf = 0, lb = 0;
        for (int i = t; i < B_SZ; i += 256) {
            unsigned char v = stm[i];
            if (v == 0x80u || v == 0x3fu) lf = 1;
            else if (v != 0u && (i & 3) != 0) lb = 1;
        }
        if (lf) atomicOr(&fFloat, 1);
        if (lb) atomicOr(&fBool, 1);
        __syncthreads();
        if (t == 0) g_mode = fFloat ? 2 : (fBool ? 1 : 0);
        return;
    }
    const int c = blockIdx.x;
    const int n = t >> 1, lh = t & 1;
    const float* src = ftw + (size_t)n * F_SZ;
    unsigned char* dstC = g_wh + (size_t)c * WCHUNK;
#pragma unroll
    for (int s = 0; s < 2; s++) {
        const int kb = c * BK + s * 16 + lh * 8;
        float4 v0 = make_float4(0, 0, 0, 0), v1 = v0;
        if (kb + 4 <= F_SZ) v0 = *(const float4*)(src + kb);
        if (kb + 8 <= F_SZ) v1 = *(const float4*)(src + kb + 4);
        uint4 o;
        o.x = cvtH2(v0.x, v0.y);
        o.y = cvtH2(v0.z, v0.w);
        o.z = cvtH2(v1.x, v1.y);
        o.w = cvtH2(v1.z, v1.w);
        *(uint4*)(dstC + s * PL + SWZ(n, lh)) = o;
    }
}

// ---------------------------------------------------------------------------
// Kernel 0c: per-neuron W rowsum (deterministic tree reduce). 128 blocks.
// ---------------------------------------------------------------------------
__global__ void wsum_kernel(const float* __restrict__ ftw) {
    __shared__ float red[256];
    const int n = blockIdx.x;
    float s = 0.0f;
    for (int k = threadIdx.x; k < F_SZ; k += 256) s += ftw[(size_t)n * F_SZ + k];
    red[threadIdx.x] = s;
    __syncthreads();
    for (int st = 128; st; st >>= 1) {
        if (threadIdx.x < st) red[threadIdx.x] += red[threadIdx.x + st];
        __syncthreads();
    }
    if (threadIdx.x == 0) g_wsum[n] = red[0];
}

// ---------------------------------------------------------------------------
// Kernel 1: fp16 1-term FT GEMM, centered A, M_CTA=256.
// 256 thr, 8 warps (4m x 2n), warp tile 64x64, BK=32 as two k16 sub-steps,
// 2-stage cp.async pipeline, 48KB dyn smem, occ 1 (smem-bound), grid (64,2).
// ---------------------------------------------------------------------------
__global__ __launch_bounds__(256, 1)
void ft_mma_kernel(const float* __restrict__ white,
                   const float* __restrict__ black,
                   const float* __restrict__ ftb) {
    extern __shared__ char smc[];
    const int t = threadIdx.x;
    const int lane = t & 31, wid = t >> 5;
    const int wm = wid >> 1, wn = wid & 1;
    const int color = blockIdx.y;
    const int row0 = blockIdx.x * 256;
    const float* __restrict__ A = color ? black : white;
    const uint32_t base = smem_u32(smc);

    // loader: thread pair per row, 2 passes (rows r and r+128)
    const int lrow = t >> 1, lh = t & 1;
    const float* aRow0 = A + (size_t)(row0 + lrow) * F_SZ;
    const float* aRow1 = A + (size_t)(row0 + 128 + lrow) * F_SZ;
    const uint32_t aDst0 = SWZ(lrow, lh);
    const uint32_t aDst1 = SWZ(lrow + 128, lh);
    const unsigned char* wSrc = g_wh + t * 16;

    float4 aq[4];

    auto ldA = [&](int ch, int s) {
        const int kb = ch * BK + s * 16 + lh * 8;
        const bool ok0 = (kb + 4 <= F_SZ), ok1 = (kb + 8 <= F_SZ);
        aq[0] = ok0 ? *(const float4*)(aRow0 + kb) : make_float4(0, 0, 0, 0);
        aq[1] = ok1 ? *(const float4*)(aRow0 + kb + 4) : make_float4(0, 0, 0, 0);
        aq[2] = ok0 ? *(const float4*)(aRow1 + kb) : make_float4(0, 0, 0, 0);
        aq[3] = ok1 ? *(const float4*)(aRow1 + kb + 4) : make_float4(0, 0, 0, 0);
    };
    auto stsA = [&](int stg, int s) {
        char* p = smc + stg * STG_SZ + s * PLA;
        uint4 v;
        v.x = cvtH2(aq[0].x - 0.5f, aq[0].y - 0.5f);
        v.y = cvtH2(aq[0].z - 0.5f, aq[0].w - 0.5f);
        v.z = cvtH2(aq[1].x - 0.5f, aq[1].y - 0.5f);
        v.w = cvtH2(aq[1].z - 0.5f, aq[1].w - 0.5f);
        *(uint4*)(p + aDst0) = v;
        v.x = cvtH2(aq[2].x - 0.5f, aq[2].y - 0.5f);
        v.y = cvtH2(aq[2].z - 0.5f, aq[2].w - 0.5f);
        v.z = cvtH2(aq[3].x - 0.5f, aq[3].y - 0.5f);
        v.w = cvtH2(aq[3].z - 0.5f, aq[3].w - 0.5f);
        *(uint4*)(p + aDst1) = v;
    };
    auto cpW = [&](int ch, int stg) {
        const uint32_t db = base + stg * STG_SZ + W_OFF + (uint32_t)(t * 16);
        const unsigned char* s = wSrc + (size_t)ch * WCHUNK;
        asm volatile("cp.async.cg.shared.global [%0], [%1], 16;"
                     :: "r"(db), "l"(s) : "memory");
        asm volatile("cp.async.cg.shared.global [%0], [%1], 16;"
                     :: "r"(db + PL), "l"(s + PL) : "memory");
    };

    // ldmatrix lane offsets
    const uint32_t offA = SWZ(wm * 64 + (lane & 15), lane >> 4);
    const uint32_t offB = SWZ(wn * 64 + ((lane >> 4) << 3) + (lane & 7), (lane >> 3) & 1);

    float acc[4][8][4];
#pragma unroll
    for (int i = 0; i < 4; i++)
#pragma unroll
        for (int j = 0; j < 8; j++)
#pragma unroll
            for (int q = 0; q < 4; q++) acc[i][j][q] = 0.0f;

    // ---- prologue: chunk 0 -> stage 0
    cpW(0, 0);
    asm volatile("cp.async.commit_group;" ::: "memory");
    ldA(0, 0); stsA(0, 0);
    ldA(0, 1); stsA(0, 1);
    asm volatile("cp.async.wait_group 0;" ::: "memory");
    __syncthreads();

    for (int c = 0; c < NCH; ++c) {
        const int cur = c & 1, nxt = cur ^ 1;
        const bool more = (c + 1) < NCH;

        if (more) { ldA(c + 1, 0); cpW(c + 1, nxt); }
        asm volatile("cp.async.commit_group;" ::: "memory");

        const uint32_t sb = base + cur * STG_SZ;
#pragma unroll
        for (int s = 0; s < 2; s++) {
            const uint32_t aPl = sb + s * PLA;
            const uint32_t wPl = sb + W_OFF + s * PL;
            uint32_t a[4][4], b[4][4];
#pragma unroll
            for (int mi = 0; mi < 4; mi++) LDSM_X4(a[mi], aPl + offA + mi * 512);
#pragma unroll
            for (int j = 0; j < 4; j++)   LDSM_X4(b[j], wPl + offB + j * 512);
#pragma unroll
            for (int mi = 0; mi < 4; mi++)
#pragma unroll
                for (int ni = 0; ni < 8; ni++) {
                    const int q = ni >> 1, r = (ni & 1) * 2;
                    MMA16816(acc[mi][ni], a[mi], b[q][r], b[q][r + 1]);
                }
            if (s == 0 && more) { stsA(nxt, 0); ldA(c + 1, 1); }
        }
        if (more) stsA(nxt, 1);

        asm volatile("cp.async.wait_group 0;" ::: "memory");
        __syncthreads();
    }

    // ---- epilogue: bias = ftb + 0.5*rowsum, screlu -> g_scratch
    float2 bias[8];
#pragma unroll
    for (int ni = 0; ni < 8; ni++) {
        const int n = wn * 64 + ni * 8 + (lane & 3) * 2;
        float2 b = *(const float2*)(ftb + n);
        float2 ws = *(const float2*)(g_wsum + n);
        bias[ni].x = b.x + 0.5f * ws.x;
        bias[ni].y = b.y + 0.5f * ws.y;
    }
#pragma unroll
    for (int mi = 0; mi < 4; mi++) {
#pragma unroll
        for (int hf = 0; hf < 2; hf++) {
            const int m = wm * 64 + mi * 16 + (lane >> 2) + hf * 8;
            float* dstRow = g_scratch + (size_t)(row0 + m) * 256 + color * 128;
#pragma unroll
            for (int ni = 0; ni < 8; ni++) {
                const int n = wn * 64 + ni * 8 + (lane & 3) * 2;
                float2 o;
                o.x = screlu(acc[mi][ni][hf * 2 + 0] + bias[ni].x);
                o.y = screlu(acc[mi][ni][hf * 2 + 1] + bias[ni].y);
                *(float2*)(dstRow + n) = o;
            }
        }
    }
}

// ---------------------------------------------------------------------------
// Kernel 2: tail MLP. 512 blocks x 8 warps x 4 rows/warp (unchanged).
// ---------------------------------------------------------------------------
__global__ __launch_bounds__(256)
void tail_kernel(const unsigned char* __restrict__ stm,
                 const float* __restrict__ l1w, const float* __restrict__ l1b,
                 const float* __restrict__ l2w, const float* __restrict__ l2b,
                 const float* __restrict__ outw, const float* __restrict__ outb,
                 float* __restrict__ out) {
    __shared__ float l1w_s[32][260];
    __shared__ float xs[8][256];
    __shared__ float x1s[8][32];
    __shared__ float l2wT[32 * 32];
    __shared__ float l1b_s[32], l2b_s[32], outw_s[32];

    const int t = threadIdx.x;
    for (int idx = t; idx < 32 * 256; idx += 256) {
        int i = idx >> 8, k = idx & 255;
        l1w_s[i][k] = l1w[idx];
    }
    for (int idx = t; idx < 32 * 32; idx += 256) {
        int i = idx >> 5, j = idx & 31;
        l2wT[j * 32 + i] = l2w[idx];
    }
    if (t < 32) {
        l1b_s[t] = l1b[t];
        l2b_s[t] = l2b[t];
        outw_s[t] = outw[t];
    }
    __syncthreads();

    const int w = t >> 5;
    const int lane = t & 31;
    const int mode = g_mode;

#pragma unroll 1
    for (int rr = 0; rr < 4; ++rr) {
        const int r = blockIdx.x * 32 + w * 4 + rr;
        bool s;
        if (mode == 2)      s = (((const float*)(const void*)stm)[r] != 0.0f);
        else if (mode == 1) s = (stm[r] != 0u);
        else                s = (((const int*)(const void*)stm)[r] != 0);
        const int rot = s ? 128 : 0;

        const float* src = g_scratch + (size_t)r * 256;
#pragma unroll
        for (int p = 0; p < 2; p++) {
            const int fi = ((lane + 32 * p) * 4 + rot) & 255;
            *(float4*)&xs[w][(lane + 32 * p) * 4] = *(const float4*)(src + fi);
        }
        __syncwarp();

        float o1 = l1b_s[lane];
#pragma unroll 8
        for (int k4 = 0; k4 < 64; k4++) {
            float4 wv = *(const float4*)&l1w_s[lane][k4 * 4];
            float4 xv = *(const float4*)&xs[w][k4 * 4];
            o1 += wv.x * xv.x + wv.y * xv.y + wv.z * xv.z + wv.w * xv.w;
        }
        x1s[w][lane] = screlu(o1);
        __syncwarp();

        float o2 = l2b_s[lane];
#pragma unroll
        for (int j = 0; j < 32; j++)
            o2 += l2wT[j * 32 + lane] * x1s[w][j];

        float v = screlu(o2) * outw_s[lane];
#pragma unroll
        for (int off = 16; off; off >>= 1)
            v += __shfl_xor_sync(0xffffffffu, v, off);
        if (lane == 0) out[r] = v + outb[0];
        __syncwarp();
    }
}

// ---------------------------------------------------------------------------
extern "C" void kernel_launch(void* const* d_in, const int* in_sizes, int n_in,
                              void* d_out, int out_size) {
    const float* white = (const float*)d_in[0];
    const float* black = (const float*)d_in[1];
    const unsigned char* stm = (const unsigned char*)d_in[2];
    const float* ftw  = (const float*)d_in[3];
    const float* ftb  = (const float*)d_in[4];
    const float* l1w  = (const float*)d_in[5];
    const float* l1b  = (const float*)d_in[6];
    const float* l2w  = (const float*)d_in[7];
    const float* l2b  = (const float*)d_in[8];
    const float* outw = (const float*)d_in[9];
    const float* outb = (const float*)d_in[10];
    float* out = (float*)d_out;

    wprep_kernel<<<NCH + 1, 256>>>(ftw, stm);
    wsum_kernel<<<128, 256>>>(ftw);
    ft_mma_kernel<<<dim3(B_SZ / 256, 2), 256, SMEM_DYN>>>(white, black, ftb);
    tail_kernel<<<B_SZ / 32, 256>>>(stm, l1w, l1b, l2w, l2b, outw, outb, out);
}

// round 13
// speedup vs baseline: 1.1370x; 1.1370x over previous
#include <cuda_runtime.h>
#include <cuda_fp16.h>
#include <cstdint>

#define B_SZ 16384
#define F_SZ 9000
#define BK   32
#define NCH  282             // ceil(9000/32); last chunk 8 valid k
#define PLW  4096            // W sub-plane bytes: 128 rows x 32B
#define PLA  8192            // A sub-plane bytes: 256 rows x 32B
// stage layout: A_s0[8K] | A_s1[8K] | W_s0[4K] | W_s1[4K] = 24KB
#define W_OFF   16384
#define WCHUNK  8192
#define STG_SZ  24576
#define SMEM_DYN 49152       // 2 stages exactly; no static smem in ft kernel

__device__ float g_scratch[B_SZ * 256];
__device__ int g_mode;
__device__ float g_wsum[128];
__device__ unsigned char g_wh[NCH * WCHUNK];   // per-chunk [W_s0|W_s1] fp16, SWZ layout

__device__ __forceinline__ float screlu(float x) {
    x = fminf(fmaxf(x, 0.0f), 1.0f);
    return x * x;
}

__device__ __forceinline__ uint32_t smem_u32(const void* p) {
    uint32_t a;
    asm("{ .reg .u64 t; cvta.to.shared.u64 t, %1; cvt.u32.u64 %0, t; }" : "=r"(a) : "l"(p));
    return a;
}

// XOR swizzle for 32B rows: row r, 16B-half h -> conflict-free ldmatrix/STS
#define SWZ(r, h) ((uint32_t)((r) * 32 + (((h) ^ (((r) >> 2) & 1)) << 4)))

__device__ __forceinline__ uint32_t h2u(__half2 h) {
    uint32_t u;
    *(__half2*)&u = h;
    return u;
}
__device__ __forceinline__ uint32_t cvtH2(float x0, float x1) {
    return h2u(__floats2half2_rn(x0, x1));
}

#define LDSM_X4(r, addr)                                                         \
    asm volatile("ldmatrix.sync.aligned.m8n8.x4.shared.b16 {%0,%1,%2,%3}, [%4];" \
                 : "=r"((r)[0]), "=r"((r)[1]), "=r"((r)[2]), "=r"((r)[3])        \
                 : "r"(addr))

#define MMA16816(c, a, bb0, bb1)                                                 \
    asm volatile("mma.sync.aligned.m16n8k16.row.col.f32.f16.f16.f32 "            \
                 "{%0,%1,%2,%3}, {%4,%5,%6,%7}, {%8,%9}, {%0,%1,%2,%3};"         \
                 : "+f"((c)[0]), "+f"((c)[1]), "+f"((c)[2]), "+f"((c)[3])        \
                 : "r"((a)[0]), "r"((a)[1]), "r"((a)[2]), "r"((a)[3]),           \
                   "r"(bb0), "r"(bb1))

// ---------------------------------------------------------------------------
// Kernel 0: W prep (fp16 1-limb, SWZ layout) + stm dtype sniff (extra block).
// ---------------------------------------------------------------------------
__global__ void wprep_kernel(const float* __restrict__ ftw,
                             const unsigned char* __restrict__ stm) {
    const int t = threadIdx.x;
    if (blockIdx.x == NCH) {
        __shared__ int fFloat, fBool;
        if (t == 0) { fFloat = 0; fBool = 0; }
        __syncthreads();
        int lf = 0, lb = 0;
        for (int i = t; i < B_SZ; i += 256) {
            unsigned char v = stm[i];
            if (v == 0x80u || v == 0x3fu) lf = 1;
            else if (v != 0u && (i & 3) != 0) lb = 1;
        }
        if (lf) atomicOr(&fFloat, 1);
        if (lb) atomicOr(&fBool, 1);
        __syncthreads();
        if (t == 0) g_mode = fFloat ? 2 : (fBool ? 1 : 0);
        return;
    }
    const int c = blockIdx.x;
    const int n = t >> 1, lh = t & 1;
    const float* src = ftw + (size_t)n * F_SZ;
    unsigned char* dstC = g_wh + (size_t)c * WCHUNK;
#pragma unroll
    for (int s = 0; s < 2; s++) {
        const int kb = c * BK + s * 16 + lh * 8;
        float4 v0 = make_float4(0, 0, 0, 0), v1 = v0;
        if (kb + 4 <= F_SZ) v0 = *(const float4*)(src + kb);
        if (kb + 8 <= F_SZ) v1 = *(const float4*)(src + kb + 4);
        uint4 o;
        o.x = cvtH2(v0.x, v0.y);
        o.y = cvtH2(v0.z, v0.w);
        o.z = cvtH2(v1.x, v1.y);
        o.w = cvtH2(v1.z, v1.w);
        *(uint4*)(dstC + s * PLW + SWZ(n, lh)) = o;
    }
}

// ---------------------------------------------------------------------------
// Kernel 0c: per-neuron W rowsum (deterministic tree reduce). 128 blocks.
// ---------------------------------------------------------------------------
__global__ void wsum_kernel(const float* __restrict__ ftw) {
    __shared__ float red[256];
    const int n = blockIdx.x;
    float s = 0.0f;
    for (int k = threadIdx.x; k < F_SZ; k += 256) s += ftw[(size_t)n * F_SZ + k];
    red[threadIdx.x] = s;
    __syncthreads();
    for (int st = 128; st; st >>= 1) {
        if (threadIdx.x < st) red[threadIdx.x] += red[threadIdx.x + st];
        __syncthreads();
    }
    if (threadIdx.x == 0) g_wsum[n] = red[0];
}

// ---------------------------------------------------------------------------
// Kernel 1: fused FT GEMM + tail MLP. Color-merged CTA: M=256 (128 white +
// 128 black rows of the same batch slice), N=128, BK=32, 2-stage pipeline.
// 512 thr, 16 warps (4m x 4n), warp tile 64x32 -> 4 warps/SMSP preserved.
// After K-loop: epilogue to scratch, re-stage smem with tail weights,
// inline tail MLP (16 warps x 8 rows) -> out.
// ---------------------------------------------------------------------------
__global__ __launch_bounds__(512, 1)
void ft_fused_kernel(const float* __restrict__ white,
                     const float* __restrict__ black,
                     const float* __restrict__ ftb,
                     const unsigned char* __restrict__ stm,
                     const float* __restrict__ l1w, const float* __restrict__ l1b,
                     const float* __restrict__ l2w, const float* __restrict__ l2b,
                     const float* __restrict__ outw, const float* __restrict__ outb,
                     float* __restrict__ out) {
    extern __shared__ char smc[];
    const int t = threadIdx.x;
    const int lane = t & 31, wid = t >> 5;
    const int wm = wid >> 2, wn = wid & 3;
    const int row0 = blockIdx.x * 128;
    const uint32_t base = smem_u32(smc);

    // loader: thread pair per virtual row (0-127 white, 128-255 black)
    const int lrow = t >> 1, lh = t & 1;
    const float* aRow = (lrow < 128)
        ? white + (size_t)(row0 + lrow) * F_SZ
        : black + (size_t)(row0 + lrow - 128) * F_SZ;
    const uint32_t aDst = SWZ(lrow, lh);
    const unsigned char* wSrc = g_wh + t * 16;

    float4 aq[2];

    auto ldA = [&](int ch, int s) {
        const int kb = ch * BK + s * 16 + lh * 8;
        aq[0] = (kb + 4 <= F_SZ) ? *(const float4*)(aRow + kb) : make_float4(0, 0, 0, 0);
        aq[1] = (kb + 8 <= F_SZ) ? *(const float4*)(aRow + kb + 4) : make_float4(0, 0, 0, 0);
    };
    auto stsA = [&](int stg, int s) {
        uint4 v;
        v.x = cvtH2(aq[0].x - 0.5f, aq[0].y - 0.5f);
        v.y = cvtH2(aq[0].z - 0.5f, aq[0].w - 0.5f);
        v.z = cvtH2(aq[1].x - 0.5f, aq[1].y - 0.5f);
        v.w = cvtH2(aq[1].z - 0.5f, aq[1].w - 0.5f);
        *(uint4*)(smc + stg * STG_SZ + s * PLA + aDst) = v;
    };
    auto cpW = [&](int ch, int stg) {
        // 512 threads x 16B = 8KB = full [W_s0|W_s1] chunk
        asm volatile("cp.async.cg.shared.global [%0], [%1], 16;"
                     :: "r"(base + stg * STG_SZ + W_OFF + (uint32_t)(t * 16)),
                        "l"(wSrc + (size_t)ch * WCHUNK) : "memory");
    };

    // ldmatrix lane offsets
    const uint32_t offA = SWZ(wm * 64 + (lane & 15), lane >> 4);
    const uint32_t offB = SWZ(wn * 32 + ((lane >> 4) << 3) + (lane & 7), (lane >> 3) & 1);

    float acc[4][4][4];
#pragma unroll
    for (int i = 0; i < 4; i++)
#pragma unroll
        for (int j = 0; j < 4; j++)
#pragma unroll
            for (int q = 0; q < 4; q++) acc[i][j][q] = 0.0f;

    // ---- prologue: chunk 0 -> stage 0
    cpW(0, 0);
    asm volatile("cp.async.commit_group;" ::: "memory");
    ldA(0, 0); stsA(0, 0);
    ldA(0, 1); stsA(0, 1);
    asm volatile("cp.async.wait_group 0;" ::: "memory");
    __syncthreads();

    for (int c = 0; c < NCH; ++c) {
        const int cur = c & 1, nxt = cur ^ 1;
        const bool more = (c + 1) < NCH;

        if (more) { ldA(c + 1, 0); cpW(c + 1, nxt); }
        asm volatile("cp.async.commit_group;" ::: "memory");

        const uint32_t sb = base + cur * STG_SZ;
#pragma unroll
        for (int s = 0; s < 2; s++) {
            const uint32_t aPl = sb + s * PLA;
            const uint32_t wPl = sb + W_OFF + s * PLW;
            uint32_t a[4][4], b[2][4];
#pragma unroll
            for (int mi = 0; mi < 4; mi++) LDSM_X4(a[mi], aPl + offA + mi * 512);
            LDSM_X4(b[0], wPl + offB);
            LDSM_X4(b[1], wPl + offB + 512);
#pragma unroll
            for (int mi = 0; mi < 4; mi++)
#pragma unroll
                for (int ni = 0; ni < 4; ni++) {
                    const int q = ni >> 1, r = (ni & 1) * 2;
                    MMA16816(acc[mi][ni], a[mi], b[q][r], b[q][r + 1]);
                }
            if (s == 0 && more) { stsA(nxt, 0); ldA(c + 1, 1); }
        }
        if (more) stsA(nxt, 1);

        asm volatile("cp.async.wait_group 0;" ::: "memory");
        __syncthreads();
    }

    // ---- FT epilogue: bias = ftb + 0.5*rowsum, screlu -> g_scratch
    float2 bias[4];
#pragma unroll
    for (int ni = 0; ni < 4; ni++) {
        const int n = wn * 32 + ni * 8 + (lane & 3) * 2;
        float2 b = *(const float2*)(ftb + n);
        float2 ws = *(const float2*)(g_wsum + n);
        bias[ni].x = b.x + 0.5f * ws.x;
        bias[ni].y = b.y + 0.5f * ws.y;
    }
#pragma unroll
    for (int mi = 0; mi < 4; mi++) {
#pragma unroll
        for (int hf = 0; hf < 2; hf++) {
            const int vrow = wm * 64 + mi * 16 + (lane >> 2) + hf * 8;
            const int r = row0 + (vrow & 127);
            const int color = vrow >> 7;
            float* dstRow = g_scratch + (size_t)r * 256 + color * 128;
#pragma unroll
            for (int ni = 0; ni < 4; ni++) {
                const int n = wn * 32 + ni * 8 + (lane & 3) * 2;
                float2 o;
                o.x = screlu(acc[mi][ni][hf * 2 + 0] + bias[ni].x);
                o.y = screlu(acc[mi][ni][hf * 2 + 1] + bias[ni].y);
                *(float2*)(dstRow + n) = o;
            }
        }
    }

    // ---- re-stage smem with tail weights (K-loop smem now free)
    float* l1w_s = (float*)smc;                       // [32][260] padded
    float* l2wT  = (float*)(smc + 33280);             // [32*32]
    float* l1b_s = (float*)(smc + 37376);             // [32]
    float* l2b_s = (float*)(smc + 37504);             // [32]
    float* outw_s = (float*)(smc + 37632);            // [32]
    float* x1s   = (float*)(smc + 37760);             // [16][32]

    for (int idx = t; idx < 32 * 256; idx += 512) {
        int i = idx >> 8, k = idx & 255;
        l1w_s[i * 260 + k] = l1w[idx];
    }
    for (int idx = t; idx < 32 * 32; idx += 512) {
        int i = idx >> 5, j = idx & 31;
        l2wT[j * 32 + i] = l2w[idx];
    }
    if (t < 32) {
        l1b_s[t] = l1b[t];
        l2b_s[t] = l2b[t];
        outw_s[t] = outw[t];
    }
    __syncthreads();   // scratch writes + weight staging visible CTA-wide

    // ---- inline tail MLP: warp wid handles rows row0 + wid*8 .. +8
    const int mode = g_mode;
#pragma unroll 1
    for (int rr = 0; rr < 8; ++rr) {
        const int r = row0 + wid * 8 + rr;
        bool s;
        if (mode == 2)      s = (((const float*)(const void*)stm)[r] != 0.0f);
        else if (mode == 1) s = (stm[r] != 0u);
        else                s = (((const int*)(const void*)stm)[r] != 0);
        const int rot = s ? 128 : 0;

        const float* src = g_scratch + (size_t)r * 256;   // L2-hot (just written)
        float o1 = l1b_s[lane];
#pragma unroll 8
        for (int k4 = 0; k4 < 64; k4++) {
            float4 xv = *(const float4*)(src + ((k4 * 4 + rot) & 255));  // broadcast
            float4 wv = *(const float4*)&l1w_s[lane * 260 + k4 * 4];
            o1 += wv.x * xv.x + wv.y * xv.y + wv.z * xv.z + wv.w * xv.w;
        }
        x1s[wid * 32 + lane] = screlu(o1);
        __syncwarp();

        float o2 = l2b_s[lane];
#pragma unroll
        for (int j = 0; j < 32; j++)
            o2 += l2wT[j * 32 + lane] * x1s[wid * 32 + j];

        float v = screlu(o2) * outw_s[lane];
#pragma unroll
        for (int off = 16; off; off >>= 1)
            v += __shfl_xor_sync(0xffffffffu, v, off);
        if (lane == 0) out[r] = v + outb[0];
        __syncwarp();
    }
}

// ---------------------------------------------------------------------------
extern "C" void kernel_launch(void* const* d_in, const int* in_sizes, int n_in,
                              void* d_out, int out_size) {
    const float* white = (const float*)d_in[0];
    const float* black = (const float*)d_in[1];
    const unsigned char* stm = (const unsigned char*)d_in[2];
    const float* ftw  = (const float*)d_in[3];
    const float* ftb  = (const float*)d_in[4];
    const float* l1w  = (const float*)d_in[5];
    const float* l1b  = (const float*)d_in[6];
    const float* l2w  = (const float*)d_in[7];
    const float* l2b  = (const float*)d_in[8];
    const float* outw = (const float*)d_in[9];
    const float* outb = (const float*)d_in[10];
    float* out = (float*)d_out;

    wprep_kernel<<<NCH + 1, 256>>>(ftw, stm);
    wsum_kernel<<<128, 256>>>(ftw);
    ft_fused_kernel<<<B_SZ / 128, 512, SMEM_DYN>>>(
        white, black, ftb, stm, l1w, l1b, l2w, l2b, outw, outb, out);
}

// round 15
// speedup vs baseline: 1.3703x; 1.2052x over previous
#include <cuda_runtime.h>
#include <cuda_fp16.h>
#include <cstdint>

#define B_SZ 16384
#define F_SZ 9000
#define BK   64
#define NCH  141             // ceil(9000/64); last chunk 40 valid k
#define PL   4096            // sub-plane bytes: 128 rows x 32B (k16)
// stage layout: A_s0..A_s3 [16KB] | W_s0..W_s3 [16KB]
#define W_OFF   16384
#define WCHUNK  16384        // W bytes per chunk in g_wh (4 sub-planes)
#define STG_SZ  32768
#define SMEM_DYN (3 * STG_SZ)   // 98304 B; set via cudaFuncSetAttribute (R2-proven)

__device__ float g_scratch[B_SZ * 256];
__device__ int g_mode;
__device__ float g_wsum[128];
__device__ unsigned char g_wh[NCH * WCHUNK];   // per-chunk fp16 W sub-planes, SWZ layout

__device__ __forceinline__ float screlu(float x) {
    x = fminf(fmaxf(x, 0.0f), 1.0f);
    return x * x;
}

__device__ __forceinline__ uint32_t smem_u32(const void* p) {
    uint32_t a;
    asm("{ .reg .u64 t; cvta.to.shared.u64 t, %1; cvt.u32.u64 %0, t; }" : "=r"(a) : "l"(p));
    return a;
}

// XOR swizzle for 32B rows: row r, 16B-half h -> conflict-free ldmatrix/STS
#define SWZ(r, h) ((uint32_t)((r) * 32 + (((h) ^ (((r) >> 2) & 1)) << 4)))

__device__ __forceinline__ uint32_t h2u(__half2 h) {
    uint32_t u;
    *(__half2*)&u = h;
    return u;
}
__device__ __forceinline__ uint32_t cvtH2(float x0, float x1) {
    return h2u(__floats2half2_rn(x0, x1));
}

#define LDSM_X4(r, addr)                                                         \
    asm volatile("ldmatrix.sync.aligned.m8n8.x4.shared.b16 {%0,%1,%2,%3}, [%4];" \
                 : "=r"((r)[0]), "=r"((r)[1]), "=r"((r)[2]), "=r"((r)[3])        \
                 : "r"(addr))

#define MMA16816(c, a, bb0, bb1)                                                 \
    asm volatile("mma.sync.aligned.m16n8k16.row.col.f32.f16.f16.f32 "            \
                 "{%0,%1,%2,%3}, {%4,%5,%6,%7}, {%8,%9}, {%0,%1,%2,%3};"         \
                 : "+f"((c)[0]), "+f"((c)[1]), "+f"((c)[2]), "+f"((c)[3])        \
                 : "r"((a)[0]), "r"((a)[1]), "r"((a)[2]), "r"((a)[3]),           \
                   "r"(bb0), "r"(bb1))

// ---------------------------------------------------------------------------
// Kernel 0: W prep (fp16 1-limb, SWZ layout, BK=64 chunks) + stm sniff.
// ---------------------------------------------------------------------------
__global__ void wprep_kernel(const float* __restrict__ ftw,
                             const unsigned char* __restrict__ stm) {
    const int t = threadIdx.x;
    if (blockIdx.x == NCH) {
        __shared__ int fFloat, fBool;
        if (t == 0) { fFloat = 0; fBool = 0; }
        __syncthreads();
        int lf = 0, lb = 0;
        for (int i = t; i < B_SZ; i += 256) {
            unsigned char v = stm[i];
            if (v == 0x80u || v == 0x3fu) lf = 1;
            else if (v != 0u && (i & 3) != 0) lb = 1;
        }
        if (lf) atomicOr(&fFloat, 1);
        if (lb) atomicOr(&fBool, 1);
        __syncthreads();
        if (t == 0) g_mode = fFloat ? 2 : (fBool ? 1 : 0);
        return;
    }
    const int c = blockIdx.x;
    const int n = t >> 1, lh = t & 1;
    const float* src = ftw + (size_t)n * F_SZ;
    unsigned char* dstC = g_wh + (size_t)c * WCHUNK;
#pragma unroll
    for (int s = 0; s < 4; s++) {
        const int kb = c * BK + s * 16 + lh * 8;
        float4 v0 = make_float4(0, 0, 0, 0), v1 = v0;
        if (kb + 4 <= F_SZ) v0 = *(const float4*)(src + kb);
        if (kb + 8 <= F_SZ) v1 = *(const float4*)(src + kb + 4);
        uint4 o;
        o.x = cvtH2(v0.x, v0.y);
        o.y = cvtH2(v0.z, v0.w);
        o.z = cvtH2(v1.x, v1.y);
        o.w = cvtH2(v1.z, v1.w);
        *(uint4*)(dstC + s * PL + SWZ(n, lh)) = o;
    }
}

// ---------------------------------------------------------------------------
// Kernel 0c: per-neuron W rowsum (deterministic tree reduce). 128 blocks.
// ---------------------------------------------------------------------------
__global__ void wsum_kernel(const float* __restrict__ ftw) {
    __shared__ float red[256];
    const int n = blockIdx.x;
    float s = 0.0f;
    for (int k = threadIdx.x; k < F_SZ; k += 256) s += ftw[(size_t)n * F_SZ + k];
    red[threadIdx.x] = s;
    __syncthreads();
    for (int st = 128; st; st >>= 1) {
        if (threadIdx.x < st) red[threadIdx.x] += red[threadIdx.x + st];
        __syncthreads();
    }
    if (threadIdx.x == 0) g_wsum[n] = red[0];
}

// ---------------------------------------------------------------------------
// Kernel 1: fp16 1-term FT GEMM, centered A. M=128/CTA, 256 thr, 8 warps
// (2m x 4n, 64x32 tiles), BK=64 as four k16 sub-steps, 3-stage cp.async
// pipeline, 96KB dyn smem, occ 2 -> two independent CTAs per SM.
// ---------------------------------------------------------------------------
__global__ __launch_bounds__(256, 2)
void ft_mma_kernel(const float* __restrict__ white,
                   const float* __restrict__ black,
                   const float* __restrict__ ftb) {
    extern __shared__ char smc[];
    const int t = threadIdx.x;
    const int lane = t & 31, wid = t >> 5;
    const int wm = wid >> 2, wn = wid & 3;
    const int color = blockIdx.y;
    const int row0 = blockIdx.x * 128;
    const float* __restrict__ A = color ? black : white;
    const uint32_t base = smem_u32(smc);

    // loader: thread pair per row, 16B-half lh = t&1
    const int lrow = t >> 1, lh = t & 1;
    const float* aRow = A + (size_t)(row0 + lrow) * F_SZ;
    const uint32_t aDst = SWZ(lrow, lh);
    const unsigned char* wSrc = g_wh + t * 16;

    float4 aq[2];

    auto ldA = [&](int ch, int s) {
        const int kb = ch * BK + s * 16 + lh * 8;
        aq[0] = (kb + 4 <= F_SZ) ? *(const float4*)(aRow + kb) : make_float4(0, 0, 0, 0);
        aq[1] = (kb + 8 <= F_SZ) ? *(const float4*)(aRow + kb + 4) : make_float4(0, 0, 0, 0);
    };
    auto stsA = [&](int stg, int s) {
        uint4 v;
        v.x = cvtH2(aq[0].x - 0.5f, aq[0].y - 0.5f);
        v.y = cvtH2(aq[0].z - 0.5f, aq[0].w - 0.5f);
        v.z = cvtH2(aq[1].x - 0.5f, aq[1].y - 0.5f);
        v.w = cvtH2(aq[1].z - 0.5f, aq[1].w - 0.5f);
        *(uint4*)(smc + stg * STG_SZ + s * PL + aDst) = v;
    };
    auto cpW = [&](int ch, int stg) {
        const uint32_t db = base + stg * STG_SZ + W_OFF + (uint32_t)(t * 16);
        const unsigned char* s = wSrc + (size_t)ch * WCHUNK;
#pragma unroll
        for (int p = 0; p < 4; p++)
            asm volatile("cp.async.cg.shared.global [%0], [%1], 16;"
                         :: "r"(db + p * PL), "l"(s + p * PL) : "memory");
    };

    // ldmatrix lane offsets
    const uint32_t offA = SWZ(wm * 64 + (lane & 15), lane >> 4);
    const uint32_t offB = SWZ(wn * 32 + ((lane >> 4) << 3) + (lane & 7), (lane >> 3) & 1);

    float acc[4][4][4];
#pragma unroll
    for (int i = 0; i < 4; i++)
#pragma unroll
        for (int j = 0; j < 4; j++)
#pragma unroll
            for (int q = 0; q < 4; q++) acc[i][j][q] = 0.0f;

    // ---- prologue: chunks 0,1 -> stages 0,1
    cpW(0, 0);
    asm volatile("cp.async.commit_group;" ::: "memory");
#pragma unroll
    for (int s = 0; s < 4; s++) { ldA(0, s); stsA(0, s); }
    cpW(1, 1);
    asm volatile("cp.async.commit_group;" ::: "memory");
#pragma unroll
    for (int s = 0; s < 4; s++) { ldA(1, s); stsA(1, s); }
    asm volatile("cp.async.wait_group 1;" ::: "memory");
    __syncthreads();

    int stg = 0, stg2 = 2;
    for (int c = 0; c < NCH; ++c) {
        const bool more = (c + 2) < NCH;
        if (more) { ldA(c + 2, 0); cpW(c + 2, stg2); }
        asm volatile("cp.async.commit_group;" ::: "memory");

        const uint32_t sb = base + stg * STG_SZ;
#pragma unroll
        for (int s = 0; s < 4; s++) {
            const uint32_t aPl = sb + s * PL;
            const uint32_t wPl = sb + W_OFF + s * PL;
            uint32_t a[4][4], b[2][4];
#pragma unroll
            for (int mi = 0; mi < 4; mi++) LDSM_X4(a[mi], aPl + offA + mi * 512);
            LDSM_X4(b[0], wPl + offB);
            LDSM_X4(b[1], wPl + offB + 512);
#pragma unroll
            for (int mi = 0; mi < 4; mi++)
#pragma unroll
                for (int ni = 0; ni < 4; ni++) {
                    const int q = ni >> 1, r = (ni & 1) * 2;
                    MMA16816(acc[mi][ni], a[mi], b[q][r], b[q][r + 1]);
                }
            // spread next-chunk A prep across the 4 sub-steps
            if (more && s < 3) { stsA(stg2, s); ldA(c + 2, s + 1); }
        }
        if (more) stsA(stg2, 3);

        asm volatile("cp.async.wait_group 1;" ::: "memory");
        __syncthreads();

        if (++stg == 3) stg = 0;
        if (++stg2 == 3) stg2 = 0;
    }

    // ---- epilogue: bias = ftb + 0.5*rowsum, screlu -> g_scratch
    float2 bias[4];
#pragma unroll
    for (int ni = 0; ni < 4; ni++) {
        const int n = wn * 32 + ni * 8 + (lane & 3) * 2;
        float2 b = *(const float2*)(ftb + n);
        float2 ws = *(const float2*)(g_wsum + n);
        bias[ni].x = b.x + 0.5f * ws.x;
        bias[ni].y = b.y + 0.5f * ws.y;
    }
#pragma unroll
    for (int mi = 0; mi < 4; mi++) {
#pragma unroll
        for (int hf = 0; hf < 2; hf++) {
            const int m = wm * 64 + mi * 16 + (lane >> 2) + hf * 8;
            float* dstRow = g_scratch + (size_t)(row0 + m) * 256 + color * 128;
#pragma unroll
            for (int ni = 0; ni < 4; ni++) {
                const int n = wn * 32 + ni * 8 + (lane & 3) * 2;
                float2 o;
                o.x = screlu(acc[mi][ni][hf * 2 + 0] + bias[ni].x);
                o.y = screlu(acc[mi][ni][hf * 2 + 1] + bias[ni].y);
                *(float2*)(dstRow + n) = o;
            }
        }
    }
}

// ---------------------------------------------------------------------------
// Kernel 2: tail MLP. 512 blocks x 8 warps x 4 rows/warp (R11-proven).
// ---------------------------------------------------------------------------
__global__ __launch_bounds__(256)
void tail_kernel(const unsigned char* __restrict__ stm,
                 const float* __restrict__ l1w, const float* __restrict__ l1b,
                 const float* __restrict__ l2w, const float* __restrict__ l2b,
                 const float* __restrict__ outw, const float* __restrict__ outb,
                 float* __restrict__ out) {
    __shared__ float l1w_s[32][260];
    __shared__ float xs[8][256];
    __shared__ float x1s[8][32];
    __shared__ float l2wT[32 * 32];
    __shared__ float l1b_s[32], l2b_s[32], outw_s[32];

    const int t = threadIdx.x;
    for (int idx = t; idx < 32 * 256; idx += 256) {
        int i = idx >> 8, k = idx & 255;
        l1w_s[i][k] = l1w[idx];
    }
    for (int idx = t; idx < 32 * 32; idx += 256) {
        int i = idx >> 5, j = idx & 31;
        l2wT[j * 32 + i] = l2w[idx];
    }
    if (t < 32) {
        l1b_s[t] = l1b[t];
        l2b_s[t] = l2b[t];
        outw_s[t] = outw[t];
    }
    __syncthreads();

    const int w = t >> 5;
    const int lane = t & 31;
    const int mode = g_mode;

#pragma unroll 1
    for (int rr = 0; rr < 4; ++rr) {
        const int r = blockIdx.x * 32 + w * 4 + rr;
        bool s;
        if (mode == 2)      s = (((const float*)(const void*)stm)[r] != 0.0f);
        else if (mode == 1) s = (stm[r] != 0u);
        else                s = (((const int*)(const void*)stm)[r] != 0);
        const int rot = s ? 128 : 0;

        const float* src = g_scratch + (size_t)r * 256;
#pragma unroll
        for (int p = 0; p < 2; p++) {
            const int fi = ((lane + 32 * p) * 4 + rot) & 255;
            *(float4*)&xs[w][(lane + 32 * p) * 4] = *(const float4*)(src + fi);
        }
        __syncwarp();

        float o1 = l1b_s[lane];
#pragma unroll 8
        for (int k4 = 0; k4 < 64; k4++) {
            float4 wv = *(const float4*)&l1w_s[lane][k4 * 4];
            float4 xv = *(const float4*)&xs[w][k4 * 4];
            o1 += wv.x * xv.x + wv.y * xv.y + wv.z * xv.z + wv.w * xv.w;
        }
        x1s[w][lane] = screlu(o1);
        __syncwarp();

        float o2 = l2b_s[lane];
#pragma unroll
        for (int j = 0; j < 32; j++)
            o2 += l2wT[j * 32 + lane] * x1s[w][j];

        float v = screlu(o2) * outw_s[lane];
#pragma unroll
        for (int off = 16; off; off >>= 1)
            v += __shfl_xor_sync(0xffffffffu, v, off);
        if (lane == 0) out[r] = v + outb[0];
        __syncwarp();
    }
}

// ---------------------------------------------------------------------------
extern "C" void kernel_launch(void* const* d_in, const int* in_sizes, int n_in,
                              void* d_out, int out_size) {
    const float* white = (const float*)d_in[0];
    const float* black = (const float*)d_in[1];
    const unsigned char* stm = (const unsigned char*)d_in[2];
    const float* ftw  = (const float*)d_in[3];
    const float* ftb  = (const float*)d_in[4];
    const float* l1w  = (const float*)d_in[5];
    const float* l1b  = (const float*)d_in[6];
    const float* l2w  = (const float*)d_in[7];
    const float* l2b  = (const float*)d_in[8];
    const float* outw = (const float*)d_in[9];
    const float* outb = (const float*)d_in[10];
    float* out = (float*)d_out;

    static int smem_set = 0;
    if (!smem_set) {
        cudaFuncSetAttribute(ft_mma_kernel,
                             cudaFuncAttributeMaxDynamicSharedMemorySize, SMEM_DYN);
        smem_set = 1;
    }

    wprep_kernel<<<NCH + 1, 256>>>(ftw, stm);
    wsum_kernel<<<128, 256>>>(ftw);
    ft_mma_kernel<<<dim3(B_SZ / 128, 2), 256, SMEM_DYN>>>(white, black, ftb);
    tail_kernel<<<B_SZ / 32, 256>>>(stm, l1w, l1b, l2w, l2b, outw, outb, out);
}